// round 14
// baseline (speedup 1.0000x reference)
#include <cuda_runtime.h>
#include <cstdint>
#include <math.h>

#define BB   2
#define SS   1024
#define DM   2048
#define NH   32
#define NKV  8
#define DK   64
#define MTOK (BB * SS)          // 2048 tokens
#define KVD  (NKV * DK)         // 512
#define BQ   128
#define BJ   64
#define STAGES 2

// ---------------- scratch (device globals: no allocations allowed) ----------
__device__ float g_q[(size_t)MTOK * DM];
__device__ float g_k[(size_t)MTOK * KVD];
__device__ float g_v[(size_t)MTOK * KVD];
__device__ float g_attn[(size_t)MTOK * DM];
__device__ float g_xr[(size_t)MTOK * DM];    // tf32-rounded x
__device__ float g_wq[(size_t)DM * DM];
__device__ float g_wk[(size_t)DM * KVD];
__device__ float g_wv[(size_t)DM * KVD];
__device__ float g_wo[(size_t)DM * DM];

// ---------------- helpers ---------------------------------------------------
__device__ __forceinline__ uint32_t f2tf(float f) {
    uint32_t r;
    asm("cvt.rna.tf32.f32 %0, %1;" : "=r"(r) : "f"(f));
    return r;
}
__device__ __forceinline__ void mma16n8k8(float* c, const uint32_t* a,
                                          uint32_t b0, uint32_t b1) {
    asm volatile(
        "mma.sync.aligned.m16n8k8.row.col.f32.tf32.tf32.f32 "
        "{%0,%1,%2,%3}, {%4,%5,%6,%7}, {%8,%9}, {%0,%1,%2,%3};"
        : "+f"(c[0]), "+f"(c[1]), "+f"(c[2]), "+f"(c[3])
        : "r"(a[0]), "r"(a[1]), "r"(a[2]), "r"(a[3]), "r"(b0), "r"(b1));
}
__device__ __forceinline__ void ldsm4(uint32_t* r, uint32_t saddr) {
    asm volatile("ldmatrix.sync.aligned.m8n8.x4.shared.b16 {%0,%1,%2,%3}, [%4];"
        : "=r"(r[0]), "=r"(r[1]), "=r"(r[2]), "=r"(r[3]) : "r"(saddr));
}
__device__ __forceinline__ void cp16(void* smem, const void* g) {
    uint32_t s = (uint32_t)__cvta_generic_to_shared(smem);
    asm volatile("cp.async.cg.shared.global [%0], [%1], 16;" :: "r"(s), "l"(g));
}
#define CP_COMMIT() asm volatile("cp.async.commit_group;" ::: "memory")
#define CP_WAIT1()  asm volatile("cp.async.wait_group 1;" ::: "memory")
#define CP_WAIT0()  asm volatile("cp.async.wait_group 0;" ::: "memory")

// --------- fused tf32 pre-round: ONE launch for x + all 4 weights -----------
__global__ __launch_bounds__(256) void round_all_kernel(
    const float* __restrict__ x,  float* __restrict__ xr,
    const float* __restrict__ wq, float* __restrict__ wqr,
    const float* __restrict__ wk, float* __restrict__ wkr,
    const float* __restrict__ wv, float* __restrict__ wvr,
    const float* __restrict__ wo, float* __restrict__ wor)
{
    const int N_X = MTOK * DM / 4, N_BIG = DM * DM / 4, N_SM = DM * KVD / 4;
    const int total = N_X + 2 * N_BIG + 2 * N_SM;
    const int stride = gridDim.x * blockDim.x;
    for (int i = blockIdx.x * blockDim.x + threadIdx.x; i < total; i += stride) {
        const float* s; float* d; int j = i;
        if (j < N_X)                { s = x;  d = xr;  }
        else if ((j -= N_X) < N_BIG)  { s = wq; d = wqr; }
        else if ((j -= N_BIG) < N_SM) { s = wk; d = wkr; }
        else if ((j -= N_SM) < N_SM)  { s = wv; d = wvr; }
        else { j -= N_SM;             s = wo; d = wor; }
        float4 v = ((const float4*)s)[j];
        ((uint4*)d)[j] = make_uint4(f2tf(v.x), f2tf(v.y), f2tf(v.z), f2tf(v.w));
    }
}

// ==== tf32 GEMM core (pre-rounded inputs): C = A @ W + bias =================
// 128x128 CTA tile, BK=32, 256 threads, 8 warps (2m x 4n), 2-stage cp.async
// (70 KB SMEM -> 2 CTAs/SM), A-fragments via ldmatrix.x4.
__device__ __forceinline__ void gemm_core(
    const float* __restrict__ A, const float* __restrict__ W,
    const float* __restrict__ bias, float* __restrict__ C,
    int Ndim, int Kdim, int m0, int n0, int do_rope, int round_out)
{
    __shared__ float As[STAGES][128][36];   // 128 rows x 32 k (+4 pad)
    __shared__ float Bs[STAGES][32][136];   // 32 k x 128 n (+8 pad)

    const int t    = threadIdx.x;
    const int wid  = t >> 5, lane = t & 31;
    const int g    = lane >> 2, tg = lane & 3;
    const int wm   = wid >> 2, wn = wid & 3;

    // staging: A 128 rows x 32 floats = 8 chunks/row, 2 thr/row, 4 chunks each
    const int ar0 = t >> 1,          akc = (t & 1) * 16;   // float offset 0 or 16
    const int bk0 = t >> 5,          bnc = (t & 31) * 4;

    const int lrow = lane & 15, lcol = (lane >> 4) * 4;
    const uint32_t a_sbase = (uint32_t)__cvta_generic_to_shared(&As[0][0][0]);

    float acc[4][4][4];
#pragma unroll
    for (int i = 0; i < 4; i++)
#pragma unroll
        for (int j = 0; j < 4; j++)
#pragma unroll
            for (int r = 0; r < 4; r++) acc[i][j][r] = 0.f;

    const int NIT = Kdim >> 5;

    // prologue: stage 0
    {
#pragma unroll
        for (int u = 0; u < 4; u++)
            cp16(&As[0][ar0][akc + u * 4],
                 &A[(size_t)(m0 + ar0) * Kdim + akc + u * 4]);
#pragma unroll
        for (int u = 0; u < 4; u++)
            cp16(&Bs[0][bk0 + u * 8][bnc],
                 &W[(size_t)(bk0 + u * 8) * Ndim + n0 + bnc]);
        CP_COMMIT();
    }

    for (int it = 0; it < NIT; it++) {
        const int sc = it & 1, sl = sc ^ 1;

        // prefetch next tile into the other buffer
        if (it + 1 < NIT) {
            const int k0 = (it + 1) << 5;
#pragma unroll
            for (int u = 0; u < 4; u++)
                cp16(&As[sl][ar0][akc + u * 4],
                     &A[(size_t)(m0 + ar0) * Kdim + k0 + akc + u * 4]);
#pragma unroll
            for (int u = 0; u < 4; u++)
                cp16(&Bs[sl][bk0 + u * 8][bnc],
                     &W[(size_t)(k0 + bk0 + u * 8) * Ndim + n0 + bnc]);
        }
        CP_COMMIT();
        CP_WAIT1();                        // current tile's group complete
        __syncthreads();

        const uint32_t a_stage = a_sbase + (uint32_t)sc * sizeof(As[0]);
#pragma unroll
        for (int ks = 0; ks < 32; ks += 8) {
            uint32_t afrag[4][4];
#pragma unroll
            for (int mf = 0; mf < 4; mf++) {
                const int row = wm * 64 + mf * 16 + lrow;
                ldsm4(afrag[mf], a_stage + (uint32_t)(row * 36 + ks + lcol) * 4);
            }
#pragma unroll
            for (int nf = 0; nf < 4; nf++) {
                const int col = wn * 32 + nf * 8 + g;
                const uint32_t b0 = __float_as_uint(Bs[sc][ks + tg][col]);
                const uint32_t b1 = __float_as_uint(Bs[sc][ks + tg + 4][col]);
#pragma unroll
                for (int mf = 0; mf < 4; mf++)
                    mma16n8k8(acc[mf][nf], afrag[mf], b0, b1);
            }
        }
        __syncthreads();                   // all warps done before overwrite
    }

    // epilogue: + bias, optional RoPE, optional tf32 rounding of output
#pragma unroll
    for (int mf = 0; mf < 4; mf++) {
        const int row = m0 + wm * 64 + mf * 16 + g;
#pragma unroll
        for (int nf = 0; nf < 4; nf++) {
            const int col = n0 + wn * 32 + nf * 8 + 2 * tg;
            const float bx = bias[col], by = bias[col + 1];
            float x0 = acc[mf][nf][0] + bx, x1 = acc[mf][nf][1] + by;
            float y0 = acc[mf][nf][2] + bx, y1 = acc[mf][nf][3] + by;
            if (do_rope) {
                const int i = (col & 63) >> 1;
                const float inv = exp2f(-13.287712379549449f * (float)i
                                        * (1.0f / 32.0f));
                float s0, c0, s1, c1;
                sincosf((float)(row & (SS - 1)) * inv, &s0, &c0);
                sincosf((float)((row + 8) & (SS - 1)) * inv, &s1, &c1);
                const float r0 = x0 * c0 - x1 * s0, r1 = x0 * s0 + x1 * c0;
                const float r2 = y0 * c1 - y1 * s1, r3 = y0 * s1 + y1 * c1;
                x0 = r0; x1 = r1; y0 = r2; y1 = r3;
            }
            if (round_out) {
                x0 = __uint_as_float(f2tf(x0)); x1 = __uint_as_float(f2tf(x1));
                y0 = __uint_as_float(f2tf(y0)); y1 = __uint_as_float(f2tf(y1));
            }
            *(float2*)&C[(size_t)row * Ndim + col]       = make_float2(x0, x1);
            *(float2*)&C[(size_t)(row + 8) * Ndim + col] = make_float2(y0, y1);
        }
    }
}

// merged QKV projection: grid.x = 24 (0-15 Q, 16-19 K, 20-23 V)
__global__ __launch_bounds__(256) void sgemm_qkv(
    const float* __restrict__ A,
    const float* __restrict__ wq, const float* __restrict__ bq,
    const float* __restrict__ wk, const float* __restrict__ bk,
    const float* __restrict__ wv, const float* __restrict__ bv,
    float* __restrict__ q, float* __restrict__ k, float* __restrict__ v)
{
    const int nx = blockIdx.x, m0 = blockIdx.y * 128;
    if (nx < 16)
        gemm_core(A, wq, bq, q, DM, DM, m0, nx * 128, 1, 1);
    else if (nx < 20)
        gemm_core(A, wk, bk, k, KVD, DM, m0, (nx - 16) * 128, 1, 1);
    else
        gemm_core(A, wv, bv, v, KVD, DM, m0, (nx - 20) * 128, 0, 1);
}

// generic single GEMM (output projection)
__global__ __launch_bounds__(256) void sgemm_mma(
    const float* __restrict__ A, const float* __restrict__ W,
    const float* __restrict__ bias, float* __restrict__ C,
    int Ndim, int Kdim, int do_rope, int round_out)
{
    gemm_core(A, W, bias, C, Ndim, Kdim, blockIdx.y * 128, blockIdx.x * 128,
              do_rope, round_out);
}

// ============ fused flash attention (tf32 mma, K/P via ldmatrix) ============
__global__ __launch_bounds__(256, 2) void flash_kernel()
{
    __shared__ float Ks[2][64][68];    // K tile: [j][d] (rows = n for QK)
    __shared__ float Vs[2][64][72];    // V tile: [j][d] (scalar B loads)
    __shared__ float QPs[128][68];     // Q tile, then P strips (rows = m)

    const int qt = gridDim.x - 1 - blockIdx.x;
    const int bh = blockIdx.y;
    const int h = bh & (NH - 1), b = bh >> 5, hk = h >> 2;
    const int q0 = qt * BQ;
    const int t = threadIdx.x, w = t >> 5, lane = t & 31;
    const int g = lane >> 2, tg = lane & 3;
    const int r0 = w * 16 + g;

    const int lrow = lane & 15, lcol = (lane >> 4) * 4;            // A-style
    const int brow = (lane & 7) + ((lane >> 4) << 3);              // B-style
    const int bkc  = ((lane >> 3) & 1) * 4;
    const uint32_t ks_sbase  = (uint32_t)__cvta_generic_to_shared(&Ks[0][0][0]);
    const uint32_t qps_sbase = (uint32_t)__cvta_generic_to_shared(&QPs[0][0]);

    const float* kbase = g_k + (size_t)b * SS * KVD + hk * 64;
    const float* vbase = g_v + (size_t)b * SS * KVD + hk * 64;

    {
        const float* qbase = g_q + (size_t)(b * SS + q0) * DM + h * 64;
#pragma unroll
        for (int u = 0; u < 8; u++) {
            const int c = t + 256 * u;
            const int r = c >> 4, dc = (c & 15) * 4;
            cp16(&QPs[r][dc], qbase + (size_t)r * DM + dc);
        }
#pragma unroll
        for (int u = 0; u < 4; u++) {
            const int c = t + 256 * u;
            const int r = c >> 4, dc = (c & 15) * 4;
            cp16(&Ks[0][r][dc], kbase + (size_t)r * KVD + dc);
            cp16(&Vs[0][r][dc], vbase + (size_t)r * KVD + dc);
        }
        CP_COMMIT();
        CP_WAIT0();
        __syncthreads();
    }

    uint32_t qf[8][4];
#pragma unroll
    for (int ks = 0; ks < 8; ks++)
        ldsm4(qf[ks], qps_sbase + (uint32_t)((w * 16 + lrow) * 68 + ks * 8 + lcol) * 4);

    float o[8][4];
#pragma unroll
    for (int i = 0; i < 8; i++)
#pragma unroll
        for (int j = 0; j < 4; j++) o[i][j] = 0.f;
    float m0v = -INFINITY, m1v = -INFINITY, l0 = 0.f, l1 = 0.f;

    const int njt = 2 * qt + 2;
    for (int jt = 0; jt < njt; jt++) {
        const int bf = jt & 1;
        __syncthreads();

        if (jt + 1 < njt) {
            const int jn = (jt + 1) * BJ;
#pragma unroll
            for (int u = 0; u < 4; u++) {
                const int c = t + 256 * u;
                const int r = c >> 4, dc = (c & 15) * 4;
                cp16(&Ks[bf ^ 1][r][dc], kbase + (size_t)(jn + r) * KVD + dc);
                cp16(&Vs[bf ^ 1][r][dc], vbase + (size_t)(jn + r) * KVD + dc);
            }
        }
        CP_COMMIT();
        CP_WAIT1();
        __syncthreads();

        const uint32_t kstage = ks_sbase + (uint32_t)bf * sizeof(Ks[0]);

        // ---- S = Q K^T (K B-frags via ldmatrix) ----
        float sf[8][4];
#pragma unroll
        for (int i = 0; i < 8; i++)
#pragma unroll
            for (int j = 0; j < 4; j++) sf[i][j] = 0.f;
#pragma unroll
        for (int ks = 0; ks < 8; ks++)
#pragma unroll
            for (int p = 0; p < 4; p++) {
                uint32_t bf4[4];
                ldsm4(bf4, kstage + (uint32_t)((p * 16 + brow) * 68 + ks * 8 + bkc) * 4);
                mma16n8k8(sf[p * 2],     qf[ks], bf4[0], bf4[1]);
                mma16n8k8(sf[p * 2 + 1], qf[ks], bf4[2], bf4[3]);
            }

        // ---- causal mask ----
        const int j0 = jt * BJ;
        if (j0 + BJ - 1 > q0 + w * 16) {
            const int ra = q0 + r0, rb = ra + 8;
#pragma unroll
            for (int nf = 0; nf < 8; nf++) {
                const int c = j0 + nf * 8 + 2 * tg;
                if (c     > ra) sf[nf][0] = -INFINITY;
                if (c + 1 > ra) sf[nf][1] = -INFINITY;
                if (c     > rb) sf[nf][2] = -INFINITY;
                if (c + 1 > rb) sf[nf][3] = -INFINITY;
            }
        }

        // ---- online softmax ----
        float rm0 = -INFINITY, rm1 = -INFINITY;
#pragma unroll
        for (int nf = 0; nf < 8; nf++) {
            rm0 = fmaxf(rm0, fmaxf(sf[nf][0], sf[nf][1]));
            rm1 = fmaxf(rm1, fmaxf(sf[nf][2], sf[nf][3]));
        }
        rm0 = fmaxf(rm0, __shfl_xor_sync(0xffffffffu, rm0, 1));
        rm0 = fmaxf(rm0, __shfl_xor_sync(0xffffffffu, rm0, 2));
        rm1 = fmaxf(rm1, __shfl_xor_sync(0xffffffffu, rm1, 1));
        rm1 = fmaxf(rm1, __shfl_xor_sync(0xffffffffu, rm1, 2));

        const float mn0 = fmaxf(m0v, 0.125f * rm0);
        const float mn1 = fmaxf(m1v, 0.125f * rm1);
        const float a0 = __expf(m0v - mn0);
        const float a1 = __expf(m1v - mn1);
        m0v = mn0; m1v = mn1;

        float rs0 = 0.f, rs1 = 0.f;
#pragma unroll
        for (int nf = 0; nf < 8; nf++) {
            sf[nf][0] = __expf(fmaf(sf[nf][0], 0.125f, -mn0));
            sf[nf][1] = __expf(fmaf(sf[nf][1], 0.125f, -mn0));
            sf[nf][2] = __expf(fmaf(sf[nf][2], 0.125f, -mn1));
            sf[nf][3] = __expf(fmaf(sf[nf][3], 0.125f, -mn1));
            rs0 += sf[nf][0] + sf[nf][1];
            rs1 += sf[nf][2] + sf[nf][3];
        }
        rs0 += __shfl_xor_sync(0xffffffffu, rs0, 1);
        rs0 += __shfl_xor_sync(0xffffffffu, rs0, 2);
        rs1 += __shfl_xor_sync(0xffffffffu, rs1, 1);
        rs1 += __shfl_xor_sync(0xffffffffu, rs1, 2);
        l0 = l0 * a0 + rs0;
        l1 = l1 * a1 + rs1;

#pragma unroll
        for (int dn = 0; dn < 8; dn++) {
            o[dn][0] *= a0; o[dn][1] *= a0;
            o[dn][2] *= a1; o[dn][3] *= a1;
        }

        // ---- P -> SMEM (own strip) ----
#pragma unroll
        for (int nf = 0; nf < 8; nf++) {
            const int c = nf * 8 + 2 * tg;
            *(uint2*)&QPs[r0][c]     = make_uint2(f2tf(sf[nf][0]), f2tf(sf[nf][1]));
            *(uint2*)&QPs[r0 + 8][c] = make_uint2(f2tf(sf[nf][2]), f2tf(sf[nf][3]));
        }
        __syncwarp();

        // ---- O += P V (P A-frags via ldmatrix, V scalar) ----
#pragma unroll
        for (int kb = 0; kb < 8; kb++) {
            uint32_t pa[4];
            ldsm4(pa, qps_sbase + (uint32_t)((w * 16 + lrow) * 68 + kb * 8 + lcol) * 4);
#pragma unroll
            for (int dn = 0; dn < 8; dn++) {
                const uint32_t b0 = __float_as_uint(Vs[bf][kb * 8 + tg][dn * 8 + g]);
                const uint32_t b1 = __float_as_uint(Vs[bf][kb * 8 + tg + 4][dn * 8 + g]);
                mma16n8k8(o[dn], pa, b0, b1);
            }
        }
    }

    const float il0 = 1.0f / l0, il1 = 1.0f / l1;
    const size_t ra = (size_t)(b * SS + q0 + r0) * DM + h * 64;
    const size_t rb = ra + (size_t)8 * DM;
#pragma unroll
    for (int dn = 0; dn < 8; dn++) {
        const int c = dn * 8 + 2 * tg;
        *(uint2*)&g_attn[ra + c] = make_uint2(f2tf(o[dn][0] * il0), f2tf(o[dn][1] * il0));
        *(uint2*)&g_attn[rb + c] = make_uint2(f2tf(o[dn][2] * il1), f2tf(o[dn][3] * il1));
    }
}

// ---------------- launch ----------------------------------------------------
extern "C" void kernel_launch(void* const* d_in, const int* in_sizes, int n_in,
                              void* d_out, int out_size)
{
    const float* x  = (const float*)d_in[0];
    const float* Wq = (const float*)d_in[1];
    const float* bq = (const float*)d_in[2];
    const float* Wk = (const float*)d_in[3];
    const float* bk = (const float*)d_in[4];
    const float* Wv = (const float*)d_in[5];
    const float* bv = (const float*)d_in[6];
    const float* Wo = (const float*)d_in[7];
    const float* bo = (const float*)d_in[8];
    float* out = (float*)d_out;

    float *q, *k, *v, *attn, *xr, *wq, *wk, *wv, *wo;
    cudaGetSymbolAddress((void**)&q,    g_q);
    cudaGetSymbolAddress((void**)&k,    g_k);
    cudaGetSymbolAddress((void**)&v,    g_v);
    cudaGetSymbolAddress((void**)&attn, g_attn);
    cudaGetSymbolAddress((void**)&xr,   g_xr);
    cudaGetSymbolAddress((void**)&wq,   g_wq);
    cudaGetSymbolAddress((void**)&wk,   g_wk);
    cudaGetSymbolAddress((void**)&wv,   g_wv);
    cudaGetSymbolAddress((void**)&wo,   g_wo);

    // single fused pre-round launch (x + all weights)
    round_all_kernel<<<1184, 256>>>(x, xr, Wq, wq, Wk, wk, Wv, wv, Wo, wo);

    // merged Q/K/V projections (RoPE fused into Q/K epilogues)
    sgemm_qkv<<<dim3(24, MTOK / 128), 256>>>(xr, wq, bq, wk, bk, wv, bv, q, k, v);

    // fused attention (emits tf32-rounded attn)
    flash_kernel<<<dim3(SS / BQ, BB * NH), 256>>>();

    // output projection (full-precision fp32 output)
    sgemm_mma<<<dim3(DM / 128, MTOK / 128), 256>>>(attn, wo, bo, out, DM, DM, 0, 0);
}

// round 16
// speedup vs baseline: 1.1694x; 1.1694x over previous
#include <cuda_runtime.h>
#include <cstdint>
#include <math.h>

#define BB   2
#define SS   1024
#define DM   2048
#define NH   32
#define NKV  8
#define DK   64
#define MTOK (BB * SS)          // 2048 tokens
#define KVD  (NKV * DK)         // 512
#define BQ   128
#define BJ   64
#define STAGES 3

// ---------------- scratch (device globals: no allocations allowed) ----------
__device__ float g_q[(size_t)MTOK * DM];
__device__ float g_k[(size_t)MTOK * KVD];
__device__ float g_v[(size_t)MTOK * KVD];
__device__ float g_attn[(size_t)MTOK * DM];
__device__ float g_xr[(size_t)MTOK * DM];    // tf32-rounded x
__device__ float g_wq[(size_t)DM * DM];
__device__ float g_wk[(size_t)DM * KVD];
__device__ float g_wv[(size_t)DM * KVD];
__device__ float g_wo[(size_t)DM * DM];

// ---------------- helpers ---------------------------------------------------
__device__ __forceinline__ uint32_t f2tf(float f) {
    uint32_t r;
    asm("cvt.rna.tf32.f32 %0, %1;" : "=r"(r) : "f"(f));
    return r;
}
__device__ __forceinline__ void mma16n8k8(float* c, const uint32_t* a,
                                          uint32_t b0, uint32_t b1) {
    asm volatile(
        "mma.sync.aligned.m16n8k8.row.col.f32.tf32.tf32.f32 "
        "{%0,%1,%2,%3}, {%4,%5,%6,%7}, {%8,%9}, {%0,%1,%2,%3};"
        : "+f"(c[0]), "+f"(c[1]), "+f"(c[2]), "+f"(c[3])
        : "r"(a[0]), "r"(a[1]), "r"(a[2]), "r"(a[3]), "r"(b0), "r"(b1));
}
__device__ __forceinline__ void ldsm4(uint32_t* r, uint32_t saddr) {
    asm volatile("ldmatrix.sync.aligned.m8n8.x4.shared.b16 {%0,%1,%2,%3}, [%4];"
        : "=r"(r[0]), "=r"(r[1]), "=r"(r[2]), "=r"(r[3]) : "r"(saddr));
}
__device__ __forceinline__ void cp16(void* smem, const void* g) {
    uint32_t s = (uint32_t)__cvta_generic_to_shared(smem);
    asm volatile("cp.async.cg.shared.global [%0], [%1], 16;" :: "r"(s), "l"(g));
}
#define CP_COMMIT() asm volatile("cp.async.commit_group;" ::: "memory")
#define CP_WAIT1()  asm volatile("cp.async.wait_group 1;" ::: "memory")
#define CP_WAIT0()  asm volatile("cp.async.wait_group 0;" ::: "memory")

// --------- fused tf32 pre-round: ONE launch for x + all 4 weights -----------
__global__ __launch_bounds__(256) void round_all_kernel(
    const float* __restrict__ x,  float* __restrict__ xr,
    const float* __restrict__ wq, float* __restrict__ wqr,
    const float* __restrict__ wk, float* __restrict__ wkr,
    const float* __restrict__ wv, float* __restrict__ wvr,
    const float* __restrict__ wo, float* __restrict__ wor)
{
    const int N_X = MTOK * DM / 4, N_BIG = DM * DM / 4, N_SM = DM * KVD / 4;
    const int total = N_X + 2 * N_BIG + 2 * N_SM;
    const int stride = gridDim.x * blockDim.x;
    for (int i = blockIdx.x * blockDim.x + threadIdx.x; i < total; i += stride) {
        const float* s; float* d; int j = i;
        if (j < N_X)                { s = x;  d = xr;  }
        else if ((j -= N_X) < N_BIG)  { s = wq; d = wqr; }
        else if ((j -= N_BIG) < N_SM) { s = wk; d = wkr; }
        else if ((j -= N_SM) < N_SM)  { s = wv; d = wvr; }
        else { j -= N_SM;             s = wo; d = wor; }
        float4 v = ((const float4*)s)[j];
        ((uint4*)d)[j] = make_uint4(f2tf(v.x), f2tf(v.y), f2tf(v.z), f2tf(v.w));
    }
}

// ==== tf32 GEMM core (pre-rounded inputs): C = A @ W + bias =================
// 128x128 CTA tile, BK=16, 256 threads, 8 warps (2m x 4n), 3-stage cp.async,
// A-fragments via ldmatrix.x4 (R11-proven config: 56 KB SMEM, 2 CTAs/SM).
__device__ __forceinline__ void gemm_core(
    const float* __restrict__ A, const float* __restrict__ W,
    const float* __restrict__ bias, float* __restrict__ C,
    int Ndim, int Kdim, int m0, int n0, int do_rope, int round_out)
{
    __shared__ float As[STAGES][128][20];
    __shared__ float Bs[STAGES][16][136];

    const int t    = threadIdx.x;
    const int wid  = t >> 5, lane = t & 31;
    const int g    = lane >> 2, tg = lane & 3;
    const int wm   = wid >> 2, wn = wid & 3;

    const int ar0 = t >> 2,  akc = (t & 3) * 4;
    const int bk0 = t >> 5,  bcc = (t & 31) * 4;

    const int lrow = lane & 15, lcol = (lane >> 4) * 4;
    const uint32_t a_sbase = (uint32_t)__cvta_generic_to_shared(&As[0][0][0]);

    float acc[4][4][4];
#pragma unroll
    for (int i = 0; i < 4; i++)
#pragma unroll
        for (int j = 0; j < 4; j++)
#pragma unroll
            for (int r = 0; r < 4; r++) acc[i][j][r] = 0.f;

    const int NIT = Kdim >> 4;

#pragma unroll
    for (int s = 0; s < 2; s++) {
        const int k0 = s << 4;
        cp16(&As[s][ar0][akc],      &A[(size_t)(m0 + ar0) * Kdim + k0 + akc]);
        cp16(&As[s][ar0 + 64][akc], &A[(size_t)(m0 + ar0 + 64) * Kdim + k0 + akc]);
        cp16(&Bs[s][bk0][bcc],      &W[(size_t)(k0 + bk0) * Ndim + n0 + bcc]);
        cp16(&Bs[s][bk0 + 8][bcc],  &W[(size_t)(k0 + bk0 + 8) * Ndim + n0 + bcc]);
        CP_COMMIT();
    }

    int sc = 0, sl = 2;
    for (int it = 0; it < NIT; it++) {
        CP_WAIT1();
        __syncthreads();

        if (it + 2 < NIT) {
            const int k0 = (it + 2) << 4;
            cp16(&As[sl][ar0][akc],      &A[(size_t)(m0 + ar0) * Kdim + k0 + akc]);
            cp16(&As[sl][ar0 + 64][akc], &A[(size_t)(m0 + ar0 + 64) * Kdim + k0 + akc]);
            cp16(&Bs[sl][bk0][bcc],      &W[(size_t)(k0 + bk0) * Ndim + n0 + bcc]);
            cp16(&Bs[sl][bk0 + 8][bcc],  &W[(size_t)(k0 + bk0 + 8) * Ndim + n0 + bcc]);
        }
        CP_COMMIT();

        const uint32_t a_stage = a_sbase + (uint32_t)sc * sizeof(As[0]);
#pragma unroll
        for (int ks = 0; ks < 16; ks += 8) {
            uint32_t afrag[4][4];
#pragma unroll
            for (int mf = 0; mf < 4; mf++) {
                const int row = wm * 64 + mf * 16 + lrow;
                ldsm4(afrag[mf], a_stage + (uint32_t)(row * 20 + ks + lcol) * 4);
            }
#pragma unroll
            for (int nf = 0; nf < 4; nf++) {
                const int col = wn * 32 + nf * 8 + g;
                const uint32_t b0 = __float_as_uint(Bs[sc][ks + tg][col]);
                const uint32_t b1 = __float_as_uint(Bs[sc][ks + tg + 4][col]);
#pragma unroll
                for (int mf = 0; mf < 4; mf++)
                    mma16n8k8(acc[mf][nf], afrag[mf], b0, b1);
            }
        }
        sc = (sc + 1 == STAGES) ? 0 : sc + 1;
        sl = (sl + 1 == STAGES) ? 0 : sl + 1;
    }

    // epilogue: + bias, optional RoPE, optional tf32 rounding of output
#pragma unroll
    for (int mf = 0; mf < 4; mf++) {
        const int row = m0 + wm * 64 + mf * 16 + g;
#pragma unroll
        for (int nf = 0; nf < 4; nf++) {
            const int col = n0 + wn * 32 + nf * 8 + 2 * tg;
            const float bx = bias[col], by = bias[col + 1];
            float x0 = acc[mf][nf][0] + bx, x1 = acc[mf][nf][1] + by;
            float y0 = acc[mf][nf][2] + bx, y1 = acc[mf][nf][3] + by;
            if (do_rope) {
                const int i = (col & 63) >> 1;
                const float inv = exp2f(-13.287712379549449f * (float)i
                                        * (1.0f / 32.0f));
                float s0, c0, s1, c1;
                sincosf((float)(row & (SS - 1)) * inv, &s0, &c0);
                sincosf((float)((row + 8) & (SS - 1)) * inv, &s1, &c1);
                const float r0 = x0 * c0 - x1 * s0, r1 = x0 * s0 + x1 * c0;
                const float r2 = y0 * c1 - y1 * s1, r3 = y0 * s1 + y1 * c1;
                x0 = r0; x1 = r1; y0 = r2; y1 = r3;
            }
            if (round_out) {
                x0 = __uint_as_float(f2tf(x0)); x1 = __uint_as_float(f2tf(x1));
                y0 = __uint_as_float(f2tf(y0)); y1 = __uint_as_float(f2tf(y1));
            }
            *(float2*)&C[(size_t)row * Ndim + col]       = make_float2(x0, x1);
            *(float2*)&C[(size_t)(row + 8) * Ndim + col] = make_float2(y0, y1);
        }
    }
}

// merged QKV projection: grid.x = 24 (0-15 Q, 16-19 K, 20-23 V)
__global__ __launch_bounds__(256, 2) void sgemm_qkv(
    const float* __restrict__ A,
    const float* __restrict__ wq, const float* __restrict__ bq,
    const float* __restrict__ wk, const float* __restrict__ bk,
    const float* __restrict__ wv, const float* __restrict__ bv,
    float* __restrict__ q, float* __restrict__ k, float* __restrict__ v)
{
    const int nx = blockIdx.x, m0 = blockIdx.y * 128;
    if (nx < 16)
        gemm_core(A, wq, bq, q, DM, DM, m0, nx * 128, 1, 1);
    else if (nx < 20)
        gemm_core(A, wk, bk, k, KVD, DM, m0, (nx - 16) * 128, 1, 1);
    else
        gemm_core(A, wv, bv, v, KVD, DM, m0, (nx - 20) * 128, 0, 1);
}

// generic single GEMM (output projection)
__global__ __launch_bounds__(256, 2) void sgemm_mma(
    const float* __restrict__ A, const float* __restrict__ W,
    const float* __restrict__ bias, float* __restrict__ C,
    int Ndim, int Kdim, int do_rope, int round_out)
{
    gemm_core(A, W, bias, C, Ndim, Kdim, blockIdx.y * 128, blockIdx.x * 128,
              do_rope, round_out);
}

// ============ fused flash attention (tf32 mma, K/P via ldmatrix) ============
__global__ __launch_bounds__(256, 2) void flash_kernel()
{
    __shared__ float Ks[2][64][68];    // K tile: [j][d] (rows = n for QK)
    __shared__ float Vs[2][64][72];    // V tile: [j][d] (scalar B loads)
    __shared__ float QPs[128][68];     // Q tile, then P strips (rows = m)

    const int qt = gridDim.x - 1 - blockIdx.x;
    const int bh = blockIdx.y;
    const int h = bh & (NH - 1), b = bh >> 5, hk = h >> 2;
    const int q0 = qt * BQ;
    const int t = threadIdx.x, w = t >> 5, lane = t & 31;
    const int g = lane >> 2, tg = lane & 3;
    const int r0 = w * 16 + g;

    const int lrow = lane & 15, lcol = (lane >> 4) * 4;            // A-style
    const int brow = (lane & 7) + ((lane >> 4) << 3);              // B-style
    const int bkc  = ((lane >> 3) & 1) * 4;
    const uint32_t ks_sbase  = (uint32_t)__cvta_generic_to_shared(&Ks[0][0][0]);
    const uint32_t qps_sbase = (uint32_t)__cvta_generic_to_shared(&QPs[0][0]);

    const float* kbase = g_k + (size_t)b * SS * KVD + hk * 64;
    const float* vbase = g_v + (size_t)b * SS * KVD + hk * 64;

    {
        const float* qbase = g_q + (size_t)(b * SS + q0) * DM + h * 64;
#pragma unroll
        for (int u = 0; u < 8; u++) {
            const int c = t + 256 * u;
            const int r = c >> 4, dc = (c & 15) * 4;
            cp16(&QPs[r][dc], qbase + (size_t)r * DM + dc);
        }
#pragma unroll
        for (int u = 0; u < 4; u++) {
            const int c = t + 256 * u;
            const int r = c >> 4, dc = (c & 15) * 4;
            cp16(&Ks[0][r][dc], kbase + (size_t)r * KVD + dc);
            cp16(&Vs[0][r][dc], vbase + (size_t)r * KVD + dc);
        }
        CP_COMMIT();
        CP_WAIT0();
        __syncthreads();
    }

    uint32_t qf[8][4];
#pragma unroll
    for (int ks = 0; ks < 8; ks++)
        ldsm4(qf[ks], qps_sbase + (uint32_t)((w * 16 + lrow) * 68 + ks * 8 + lcol) * 4);

    float o[8][4];
#pragma unroll
    for (int i = 0; i < 8; i++)
#pragma unroll
        for (int j = 0; j < 4; j++) o[i][j] = 0.f;
    float m0v = -INFINITY, m1v = -INFINITY, l0 = 0.f, l1 = 0.f;

    const int njt = 2 * qt + 2;
    for (int jt = 0; jt < njt; jt++) {
        const int bf = jt & 1;
        __syncthreads();

        if (jt + 1 < njt) {
            const int jn = (jt + 1) * BJ;
#pragma unroll
            for (int u = 0; u < 4; u++) {
                const int c = t + 256 * u;
                const int r = c >> 4, dc = (c & 15) * 4;
                cp16(&Ks[bf ^ 1][r][dc], kbase + (size_t)(jn + r) * KVD + dc);
                cp16(&Vs[bf ^ 1][r][dc], vbase + (size_t)(jn + r) * KVD + dc);
            }
        }
        CP_COMMIT();
        CP_WAIT1();
        __syncthreads();

        const uint32_t kstage = ks_sbase + (uint32_t)bf * sizeof(Ks[0]);

        // ---- S = Q K^T (K B-frags via ldmatrix) ----
        float sf[8][4];
#pragma unroll
        for (int i = 0; i < 8; i++)
#pragma unroll
            for (int j = 0; j < 4; j++) sf[i][j] = 0.f;
#pragma unroll
        for (int ks = 0; ks < 8; ks++)
#pragma unroll
            for (int p = 0; p < 4; p++) {
                uint32_t bf4[4];
                ldsm4(bf4, kstage + (uint32_t)((p * 16 + brow) * 68 + ks * 8 + bkc) * 4);
                mma16n8k8(sf[p * 2],     qf[ks], bf4[0], bf4[1]);
                mma16n8k8(sf[p * 2 + 1], qf[ks], bf4[2], bf4[3]);
            }

        // ---- causal mask ----
        const int j0 = jt * BJ;
        if (j0 + BJ - 1 > q0 + w * 16) {
            const int ra = q0 + r0, rb = ra + 8;
#pragma unroll
            for (int nf = 0; nf < 8; nf++) {
                const int c = j0 + nf * 8 + 2 * tg;
                if (c     > ra) sf[nf][0] = -INFINITY;
                if (c + 1 > ra) sf[nf][1] = -INFINITY;
                if (c     > rb) sf[nf][2] = -INFINITY;
                if (c + 1 > rb) sf[nf][3] = -INFINITY;
            }
        }

        // ---- online softmax ----
        float rm0 = -INFINITY, rm1 = -INFINITY;
#pragma unroll
        for (int nf = 0; nf < 8; nf++) {
            rm0 = fmaxf(rm0, fmaxf(sf[nf][0], sf[nf][1]));
            rm1 = fmaxf(rm1, fmaxf(sf[nf][2], sf[nf][3]));
        }
        rm0 = fmaxf(rm0, __shfl_xor_sync(0xffffffffu, rm0, 1));
        rm0 = fmaxf(rm0, __shfl_xor_sync(0xffffffffu, rm0, 2));
        rm1 = fmaxf(rm1, __shfl_xor_sync(0xffffffffu, rm1, 1));
        rm1 = fmaxf(rm1, __shfl_xor_sync(0xffffffffu, rm1, 2));

        const float mn0 = fmaxf(m0v, 0.125f * rm0);
        const float mn1 = fmaxf(m1v, 0.125f * rm1);
        const float a0 = __expf(m0v - mn0);
        const float a1 = __expf(m1v - mn1);
        m0v = mn0; m1v = mn1;

        float rs0 = 0.f, rs1 = 0.f;
#pragma unroll
        for (int nf = 0; nf < 8; nf++) {
            sf[nf][0] = __expf(fmaf(sf[nf][0], 0.125f, -mn0));
            sf[nf][1] = __expf(fmaf(sf[nf][1], 0.125f, -mn0));
            sf[nf][2] = __expf(fmaf(sf[nf][2], 0.125f, -mn1));
            sf[nf][3] = __expf(fmaf(sf[nf][3], 0.125f, -mn1));
            rs0 += sf[nf][0] + sf[nf][1];
            rs1 += sf[nf][2] + sf[nf][3];
        }
        rs0 += __shfl_xor_sync(0xffffffffu, rs0, 1);
        rs0 += __shfl_xor_sync(0xffffffffu, rs0, 2);
        rs1 += __shfl_xor_sync(0xffffffffu, rs1, 1);
        rs1 += __shfl_xor_sync(0xffffffffu, rs1, 2);
        l0 = l0 * a0 + rs0;
        l1 = l1 * a1 + rs1;

#pragma unroll
        for (int dn = 0; dn < 8; dn++) {
            o[dn][0] *= a0; o[dn][1] *= a0;
            o[dn][2] *= a1; o[dn][3] *= a1;
        }

        // ---- P -> SMEM (own strip) ----
#pragma unroll
        for (int nf = 0; nf < 8; nf++) {
            const int c = nf * 8 + 2 * tg;
            *(uint2*)&QPs[r0][c]     = make_uint2(f2tf(sf[nf][0]), f2tf(sf[nf][1]));
            *(uint2*)&QPs[r0 + 8][c] = make_uint2(f2tf(sf[nf][2]), f2tf(sf[nf][3]));
        }
        __syncwarp();

        // ---- O += P V (P A-frags via ldmatrix, V scalar) ----
#pragma unroll
        for (int kb = 0; kb < 8; kb++) {
            uint32_t pa[4];
            ldsm4(pa, qps_sbase + (uint32_t)((w * 16 + lrow) * 68 + kb * 8 + lcol) * 4);
#pragma unroll
            for (int dn = 0; dn < 8; dn++) {
                const uint32_t b0 = __float_as_uint(Vs[bf][kb * 8 + tg][dn * 8 + g]);
                const uint32_t b1 = __float_as_uint(Vs[bf][kb * 8 + tg + 4][dn * 8 + g]);
                mma16n8k8(o[dn], pa, b0, b1);
            }
        }
    }

    const float il0 = 1.0f / l0, il1 = 1.0f / l1;
    const size_t ra = (size_t)(b * SS + q0 + r0) * DM + h * 64;
    const size_t rb = ra + (size_t)8 * DM;
#pragma unroll
    for (int dn = 0; dn < 8; dn++) {
        const int c = dn * 8 + 2 * tg;
        *(uint2*)&g_attn[ra + c] = make_uint2(f2tf(o[dn][0] * il0), f2tf(o[dn][1] * il0));
        *(uint2*)&g_attn[rb + c] = make_uint2(f2tf(o[dn][2] * il1), f2tf(o[dn][3] * il1));
    }
}

// ---------------- launch ----------------------------------------------------
extern "C" void kernel_launch(void* const* d_in, const int* in_sizes, int n_in,
                              void* d_out, int out_size)
{
    const float* x  = (const float*)d_in[0];
    const float* Wq = (const float*)d_in[1];
    const float* bq = (const float*)d_in[2];
    const float* Wk = (const float*)d_in[3];
    const float* bk = (const float*)d_in[4];
    const float* Wv = (const float*)d_in[5];
    const float* bv = (const float*)d_in[6];
    const float* Wo = (const float*)d_in[7];
    const float* bo = (const float*)d_in[8];
    float* out = (float*)d_out;

    float *q, *k, *v, *attn, *xr, *wq, *wk, *wv, *wo;
    cudaGetSymbolAddress((void**)&q,    g_q);
    cudaGetSymbolAddress((void**)&k,    g_k);
    cudaGetSymbolAddress((void**)&v,    g_v);
    cudaGetSymbolAddress((void**)&attn, g_attn);
    cudaGetSymbolAddress((void**)&xr,   g_xr);
    cudaGetSymbolAddress((void**)&wq,   g_wq);
    cudaGetSymbolAddress((void**)&wk,   g_wk);
    cudaGetSymbolAddress((void**)&wv,   g_wv);
    cudaGetSymbolAddress((void**)&wo,   g_wo);

    // single fused pre-round launch (x + all weights)
    round_all_kernel<<<1184, 256>>>(x, xr, Wq, wq, Wk, wk, Wv, wv, Wo, wo);

    // merged Q/K/V projections (RoPE fused into Q/K epilogues)
    sgemm_qkv<<<dim3(24, MTOK / 128), 256>>>(xr, wq, bq, wk, bk, wv, bv, q, k, v);

    // fused attention (emits tf32-rounded attn)
    flash_kernel<<<dim3(SS / BQ, BB * NH), 256>>>();

    // output projection (full-precision fp32 output)
    sgemm_mma<<<dim3(DM / 128, MTOK / 128), 256>>>(attn, wo, bo, out, DM, DM, 0, 0);
}